// round 1
// baseline (speedup 1.0000x reference)
#include <cuda_runtime.h>
#include <math.h>

#define BB   128
#define VV   128000
#define TPB  1024
#define NBIN1 4096
#define NBIN2 1024
#define CAND_MAX 4096

// monotonic float -> ordered uint32
__device__ __forceinline__ unsigned int f2ord(float f) {
    unsigned int u = __float_as_uint(f);
    return (u & 0x80000000u) ? ~u : (u | 0x80000000u);
}

__device__ float blk_excl_scan(float v, float* tmp) {
    __syncthreads();
    int lane = threadIdx.x & 31, w = threadIdx.x >> 5;
    float x = v;
    #pragma unroll
    for (int o = 1; o < 32; o <<= 1) {
        float y = __shfl_up_sync(0xffffffffu, x, o);
        if (lane >= o) x += y;
    }
    if (lane == 31) tmp[w] = x;
    __syncthreads();
    if (w == 0) {
        float s = tmp[lane];
        #pragma unroll
        for (int o = 1; o < 32; o <<= 1) {
            float y = __shfl_up_sync(0xffffffffu, s, o);
            if (lane >= o) s += y;
        }
        tmp[lane] = s;
    }
    __syncthreads();
    float pre = (w > 0) ? tmp[w - 1] : 0.0f;
    return pre + x - v;   // exclusive prefix for this thread
}

__device__ float blk_reduce_sum(float v, float* tmp) {
    __syncthreads();
    int lane = threadIdx.x & 31, w = threadIdx.x >> 5;
    #pragma unroll
    for (int o = 16; o; o >>= 1) v += __shfl_xor_sync(0xffffffffu, v, o);
    if (lane == 0) tmp[w] = v;
    __syncthreads();
    if (w == 0) {
        float x = tmp[lane];
        #pragma unroll
        for (int o = 16; o; o >>= 1) x += __shfl_xor_sync(0xffffffffu, x, o);
        if (lane == 0) tmp[0] = x;
    }
    __syncthreads();
    return tmp[0];
}

__device__ float blk_reduce_max(float v, float* tmp) {
    __syncthreads();
    int lane = threadIdx.x & 31, w = threadIdx.x >> 5;
    #pragma unroll
    for (int o = 16; o; o >>= 1) v = fmaxf(v, __shfl_xor_sync(0xffffffffu, v, o));
    if (lane == 0) tmp[w] = v;
    __syncthreads();
    if (w == 0) {
        float x = tmp[lane];
        #pragma unroll
        for (int o = 16; o; o >>= 1) x = fmaxf(x, __shfl_xor_sync(0xffffffffu, x, o));
        if (lane == 0) tmp[0] = x;
    }
    __syncthreads();
    return tmp[0];
}

struct CrossRes { int bin; float above; bool found; };

// Scan bins descending (bin NBINS-1 .. 0). Find bin c with
// cumAbove < target <= cumAbove + w[c]. Exact for integer-valued weights.
template<int NBINS>
__device__ CrossRes find_crossing(const float* wgt, float target, float* scanTmp,
                                  int* sh_r, int* sh_b, float* sh_c) {
    __syncthreads();   // wgt writes from all threads visible
    const int bpt = NBINS / TPB;
    int t = threadIdx.x;
    float s = 0.f;
    #pragma unroll
    for (int j = 0; j < bpt; j++) s += wgt[NBINS - 1 - (t * bpt + j)];
    float P = blk_excl_scan(s, scanTmp);
    if (t == 0) *sh_r = 0x7fffffff;
    __syncthreads();
    float cum = P;
    #pragma unroll
    for (int j = 0; j < bpt; j++) {
        int r = t * bpt + j;
        float wv = wgt[NBINS - 1 - r];
        if (cum < target && cum + wv >= target) atomicMin(sh_r, r);
        cum += wv;
    }
    __syncthreads();
    int fr = *sh_r;
    if (fr != 0x7fffffff) {
        cum = P;
        #pragma unroll
        for (int j = 0; j < bpt; j++) {
            int r = t * bpt + j;
            float wv = wgt[NBINS - 1 - r];
            if (r == fr) { *sh_b = NBINS - 1 - r; *sh_c = cum; }
            cum += wv;
        }
    }
    __syncthreads();
    CrossRes res;
    res.found = (fr != 0x7fffffff);
    res.bin = res.found ? *sh_b : 0;
    res.above = res.found ? *sh_c : 0.f;
    return res;
}

__global__ void __launch_bounds__(TPB, 1)
topk_topp_sample_kernel(const float* __restrict__ logits,
                        const int*   __restrict__ karr,
                        const float* __restrict__ parr,
                        const float* __restrict__ qarr,
                        float* __restrict__ out_ids,
                        float* __restrict__ out_probs)
{
    __shared__ float hist[NBIN1];     // 16 KB (also reused as weighted L1)
    __shared__ float h2[NBIN2];       // 4 KB  (levels 2/3)
    __shared__ float cand[CAND_MAX];  // 16 KB
    __shared__ float scanTmp[32];
    __shared__ float redTmp[32];
    __shared__ int   shr; __shared__ int shb; __shared__ float shc;
    __shared__ int   shn;
    __shared__ float argV[32]; __shared__ int argI[32];

    const int row = blockIdx.x;
    const int t = threadIdx.x;
    const float* lg = logits + (long long)row * VV;
    const float* qr = qarr   + (long long)row * VV;
    float* pro = out_probs + (long long)row * VV;
    const int   k = karr[row];
    const float p = parr[row];

    for (int i = t; i < NBIN1; i += TPB) hist[i] = 0.f;
    if (t == 0) shn = 0;
    __syncthreads();

    // ---- Phase A: 12-bit histogram over ordered keys + row max ----
    const float4* lg4 = reinterpret_cast<const float4*>(lg);
    const int NV4 = VV / 4;
    float lmax = -3.4e38f;
    for (int i = t; i < NV4; i += TPB) {
        float4 v = lg4[i];
        lmax = fmaxf(lmax, fmaxf(fmaxf(v.x, v.y), fmaxf(v.z, v.w)));
        atomicAdd(&hist[f2ord(v.x) >> 20], 1.f);
        atomicAdd(&hist[f2ord(v.y) >> 20], 1.f);
        atomicAdd(&hist[f2ord(v.z) >> 20], 1.f);
        atomicAdd(&hist[f2ord(v.w) >> 20], 1.f);
    }
    float M = blk_reduce_max(lmax, redTmp);

    // ---- Level-1 count select: bin containing the k-th largest ----
    CrossRes r1 = find_crossing<NBIN1>(hist, (float)k, scanTmp, &shr, &shb, &shc);
    unsigned b1 = (unsigned)r1.bin;
    float krem = (float)k - r1.above;           // rank target within bin b1
    unsigned floor1 = b1 << 20;

    // ---- Phase C: compact candidates (ou >= bin floor) into smem ----
    for (int i = t; i < NV4; i += TPB) {
        float4 v = lg4[i];
        float xs[4] = {v.x, v.y, v.z, v.w};
        #pragma unroll
        for (int j = 0; j < 4; j++) {
            float x = xs[j];
            bool take = (f2ord(x) >= floor1);
            unsigned m = __ballot_sync(0xffffffffu, take);
            if (m) {
                int lane = t & 31;
                int leader = __ffs(m) - 1;
                int base = 0;
                if (lane == leader) base = atomicAdd(&shn, __popc(m));
                base = __shfl_sync(0xffffffffu, base, leader);
                if (take) {
                    int off = base + __popc(m & ((1u << lane) - 1u));
                    if (off < CAND_MAX) cand[off] = x;
                }
            }
        }
    }
    __syncthreads();
    int n = shn; if (n > CAND_MAX) n = CAND_MAX;

    // ---- Level-2/3 count select -> exact top-k threshold (32-bit key) ----
    for (int i = t; i < NBIN2; i += TPB) h2[i] = 0.f;
    __syncthreads();
    for (int i = t; i < n; i += TPB) {
        unsigned ou = f2ord(cand[i]);
        if ((ou >> 20) == b1) atomicAdd(&h2[(ou >> 10) & 1023u], 1.f);
    }
    CrossRes r2 = find_crossing<NBIN2>(h2, krem, scanTmp, &shr, &shb, &shc);
    float krem2 = krem - r2.above;
    unsigned pfx2 = (b1 << 10) | (unsigned)r2.bin;

    for (int i = t; i < NBIN2; i += TPB) h2[i] = 0.f;
    __syncthreads();
    for (int i = t; i < n; i += TPB) {
        unsigned ou = f2ord(cand[i]);
        if ((ou >> 10) == pfx2) atomicAdd(&h2[ou & 1023u], 1.f);
    }
    CrossRes r3 = find_crossing<NBIN2>(h2, krem2, scanTmp, &shr, &shb, &shc);
    unsigned thr_ou = (pfx2 << 10) | (unsigned)r3.bin;

    // ---- Z_k = sum exp over top-k set ----
    float zs = 0.f;
    for (int i = t; i < n; i += TPB) {
        float x = cand[i];
        if (f2ord(x) >= thr_ou) zs += __expf(x - M);
    }
    float Zk = blk_reduce_sum(zs, redTmp);
    float T = p * Zk;   // keep token iff exp-weight strictly above it < T

    // ---- Weighted radix descent for top-p cutoff value t ----
    __syncthreads();
    for (int i = t; i < NBIN1; i += TPB) hist[i] = 0.f;
    __syncthreads();
    for (int i = t; i < n; i += TPB) {
        float x = cand[i]; unsigned ou = f2ord(x);
        if (ou >= thr_ou) atomicAdd(&hist[ou >> 20], __expf(x - M));
    }
    CrossRes w1 = find_crossing<NBIN1>(hist, T, scanTmp, &shr, &shb, &shc);
    unsigned t_ou;
    if (!w1.found) {
        t_ou = thr_ou;                       // everything kept
    } else {
        float T1 = T - w1.above;
        unsigned c1 = (unsigned)w1.bin;
        for (int i = t; i < NBIN2; i += TPB) h2[i] = 0.f;
        __syncthreads();
        for (int i = t; i < n; i += TPB) {
            float x = cand[i]; unsigned ou = f2ord(x);
            if (ou >= thr_ou && (ou >> 20) == c1)
                atomicAdd(&h2[(ou >> 10) & 1023u], __expf(x - M));
        }
        CrossRes w2 = find_crossing<NBIN2>(h2, T1, scanTmp, &shr, &shb, &shc);
        if (!w2.found) {
            t_ou = c1 << 20;                 // all of bin c1 kept
        } else {
            float T2 = T1 - w2.above;
            unsigned pw = (c1 << 10) | (unsigned)w2.bin;
            for (int i = t; i < NBIN2; i += TPB) h2[i] = 0.f;
            __syncthreads();
            for (int i = t; i < n; i += TPB) {
                float x = cand[i]; unsigned ou = f2ord(x);
                if (ou >= thr_ou && (ou >> 10) == pw)
                    atomicAdd(&h2[ou & 1023u], __expf(x - M));
            }
            CrossRes w3 = find_crossing<NBIN2>(h2, T2, scanTmp, &shr, &shb, &shc);
            t_ou = w3.found ? ((pw << 10) | (unsigned)w3.bin) : (pw << 10);
        }
    }
    unsigned f_ou = (t_ou > thr_ou) ? t_ou : thr_ou;  // final kept: ou >= f_ou

    // ---- Final normalizer over kept set ----
    float zf = 0.f;
    for (int i = t; i < n; i += TPB) {
        float x = cand[i];
        if (f2ord(x) >= f_ou) zf += __expf(x - M);
    }
    float Z = blk_reduce_sum(zf, redTmp);
    float invZ = 1.0f / Z;

    // ---- Phase E: write probs + fused Gumbel-max argmax ----
    const float4* q4 = reinterpret_cast<const float4*>(qr);
    float4* pr4 = reinterpret_cast<float4*>(pro);
    float bv = -1.f; int bi = 0x7fffffff;
    for (int i = t; i < NV4; i += TPB) {
        float4 lv = lg4[i];
        float4 qv = q4[i];
        float xs[4] = {lv.x, lv.y, lv.z, lv.w};
        float qs[4] = {qv.x, qv.y, qv.z, qv.w};
        float ps[4];
        #pragma unroll
        for (int j = 0; j < 4; j++) {
            float x = xs[j];
            float prob = (f2ord(x) >= f_ou) ? __expf(x - M) * invZ : 0.0f;
            ps[j] = prob;
            float ratio = prob / (-__logf(qs[j]));   // q < 1 -> denom > 0
            int idx = i * 4 + j;
            if (ratio > bv || (ratio == bv && idx < bi)) { bv = ratio; bi = idx; }
        }
        float4 ov; ov.x = ps[0]; ov.y = ps[1]; ov.z = ps[2]; ov.w = ps[3];
        pr4[i] = ov;
    }
    // argmax reduce (first-index tie-break, matching jnp.argmax)
    int lane = t & 31, wd = t >> 5;
    #pragma unroll
    for (int o = 16; o; o >>= 1) {
        float ov = __shfl_down_sync(0xffffffffu, bv, o);
        int   oi = __shfl_down_sync(0xffffffffu, bi, o);
        if (ov > bv || (ov == bv && oi < bi)) { bv = ov; bi = oi; }
    }
    if (lane == 0) { argV[wd] = bv; argI[wd] = bi; }
    __syncthreads();
    if (wd == 0) {
        bv = argV[lane]; bi = argI[lane];
        #pragma unroll
        for (int o = 16; o; o >>= 1) {
            float ov = __shfl_down_sync(0xffffffffu, bv, o);
            int   oi = __shfl_down_sync(0xffffffffu, bi, o);
            if (ov > bv || (ov == bv && oi < bi)) { bv = ov; bi = oi; }
        }
        if (lane == 0) out_ids[row] = (float)bi;
    }
}

extern "C" void kernel_launch(void* const* d_in, const int* in_sizes, int n_in,
                              void* d_out, int out_size) {
    const float* logits = (const float*)d_in[0];
    const int*   k      = (const int*)  d_in[1];
    const float* p      = (const float*)d_in[2];
    const float* q      = (const float*)d_in[3];
    float* out = (float*)d_out;
    // tuple order (sampled, probs): ids first, then probs
    float* out_ids   = out;
    float* out_probs = out + BB;
    topk_topp_sample_kernel<<<BB, TPB>>>(logits, k, p, q, out_ids, out_probs);
}

// round 4
// speedup vs baseline: 1.6105x; 1.6105x over previous
#include <cuda_runtime.h>
#include <math.h>

#define BB   128
#define VV   128000
#define NV4  (VV/4)
#define TPB  1024
#define NB1  256     // level-1: top 8 bits of ordered key
#define NB12 4096    // 12-bit refine / weighted level-1
#define NB2  1024    // weighted levels 2/3
#define CAND_MAX 6144

// monotonic float -> ordered uint32
__device__ __forceinline__ unsigned f2ord(float f) {
    unsigned u = __float_as_uint(f);
    return (u & 0x80000000u) ? ~u : (u | 0x80000000u);
}

__device__ float blk_excl_scan(float v, float* tmp) {
    __syncthreads();
    int lane = threadIdx.x & 31, w = threadIdx.x >> 5;
    float x = v;
    #pragma unroll
    for (int o = 1; o < 32; o <<= 1) {
        float y = __shfl_up_sync(0xffffffffu, x, o);
        if (lane >= o) x += y;
    }
    if (lane == 31) tmp[w] = x;
    __syncthreads();
    if (w == 0) {
        float s = tmp[lane];
        #pragma unroll
        for (int o = 1; o < 32; o <<= 1) {
            float y = __shfl_up_sync(0xffffffffu, s, o);
            if (lane >= o) s += y;
        }
        tmp[lane] = s;
    }
    __syncthreads();
    float pre = (w > 0) ? tmp[w - 1] : 0.0f;
    return pre + x - v;
}

__device__ float blk_reduce_sum(float v, float* tmp) {
    __syncthreads();
    int lane = threadIdx.x & 31, w = threadIdx.x >> 5;
    #pragma unroll
    for (int o = 16; o; o >>= 1) v += __shfl_xor_sync(0xffffffffu, v, o);
    if (lane == 0) tmp[w] = v;
    __syncthreads();
    if (w == 0) {
        float x = tmp[lane];
        #pragma unroll
        for (int o = 16; o; o >>= 1) x += __shfl_xor_sync(0xffffffffu, x, o);
        if (lane == 0) tmp[0] = x;
    }
    __syncthreads();
    return tmp[0];
}

__device__ float blk_reduce_max(float v, float* tmp) {
    __syncthreads();
    int lane = threadIdx.x & 31, w = threadIdx.x >> 5;
    #pragma unroll
    for (int o = 16; o; o >>= 1) v = fmaxf(v, __shfl_xor_sync(0xffffffffu, v, o));
    if (lane == 0) tmp[w] = v;
    __syncthreads();
    if (w == 0) {
        float x = tmp[lane];
        #pragma unroll
        for (int o = 16; o; o >>= 1) x = fmaxf(x, __shfl_xor_sync(0xffffffffu, x, o));
        if (lane == 0) tmp[0] = x;
    }
    __syncthreads();
    return tmp[0];
}

struct CrossRes { int bin; float above; bool found; };

// Scan bins descending (bin NBINS-1 .. 0). Find bin c with
// cumAbove < target <= cumAbove + w[c]. Works for NBINS <= TPB (bpt=1, guarded)
// and NBINS > TPB (bpt>1).
template<int NBINS>
__device__ CrossRes find_crossing(const float* wgt, float target, float* scanTmp,
                                  int* sh_r, int* sh_b, float* sh_c) {
    __syncthreads();
    const int bpt = (NBINS + TPB - 1) / TPB;
    int t = threadIdx.x;
    float s = 0.f;
    #pragma unroll
    for (int j = 0; j < bpt; j++) {
        int r = t * bpt + j;
        if (r < NBINS) s += wgt[NBINS - 1 - r];
    }
    float P = blk_excl_scan(s, scanTmp);
    if (t == 0) *sh_r = 0x7fffffff;
    __syncthreads();
    float cum = P;
    #pragma unroll
    for (int j = 0; j < bpt; j++) {
        int r = t * bpt + j;
        if (r < NBINS) {
            float wv = wgt[NBINS - 1 - r];
            if (cum < target && cum + wv >= target) atomicMin(sh_r, r);
            cum += wv;
        }
    }
    __syncthreads();
    int fr = *sh_r;
    if (fr != 0x7fffffff) {
        cum = P;
        #pragma unroll
        for (int j = 0; j < bpt; j++) {
            int r = t * bpt + j;
            if (r < NBINS) {
                float wv = wgt[NBINS - 1 - r];
                if (r == fr) { *sh_b = NBINS - 1 - r; *sh_c = cum; }
                cum += wv;
            }
        }
    }
    __syncthreads();
    CrossRes res;
    res.found = (fr != 0x7fffffff);
    res.bin = res.found ? *sh_b : 0;
    res.above = res.found ? *sh_c : 0.f;
    return res;
}

__global__ void __launch_bounds__(TPB, 1)
topk_topp_sample_kernel(const float* __restrict__ logits,
                        const int*   __restrict__ karr,
                        const float* __restrict__ parr,
                        const float* __restrict__ qarr,
                        float* __restrict__ out_ids,
                        float* __restrict__ out_probs)
{
    // 40 KB union buffer: phase A = 32 warp-private 256-bin int hists (32 KB);
    // later phases = hist12[4096] floats (16 KB) + cand[6144] floats (24 KB).
    __shared__ __align__(16) unsigned char sbuf[40960];
    __shared__ float h2[NB2];
    __shared__ float h8f[NB1];
    __shared__ float scanTmp[32];
    __shared__ float redTmp[32];
    __shared__ int   shr; __shared__ int shb; __shared__ float shc;
    __shared__ int   shn;
    __shared__ float argV[32]; __shared__ int argI[32];

    int*   wh     = reinterpret_cast<int*>(sbuf);            // [32][256]
    float* hist12 = reinterpret_cast<float*>(sbuf);          // [4096]
    float* cand   = reinterpret_cast<float*>(sbuf + 16384);  // [6144]

    const int row = blockIdx.x;
    const int t = threadIdx.x;
    const int lane = t & 31, warp = t >> 5;
    const float* lg = logits + (long long)row * VV;
    const float* qr = qarr   + (long long)row * VV;
    float* pro = out_probs + (long long)row * VV;
    const int   k = karr[row];
    const float p = parr[row];

    // ---- Phase A: per-warp-private 8-bit histogram + row max ----
    for (int i = t; i < 32 * NB1; i += TPB) wh[i] = 0;
    __syncthreads();

    const float4* lg4 = reinterpret_cast<const float4*>(lg);
    int* myh = wh + warp * NB1;
    float lmax = -3.4e38f;
    for (int i = t; i < NV4; i += TPB) {
        float4 v = lg4[i];
        unsigned os[4] = { f2ord(v.x), f2ord(v.y), f2ord(v.z), f2ord(v.w) };
        lmax = fmaxf(lmax, fmaxf(fmaxf(v.x, v.y), fmaxf(v.z, v.w)));
        #pragma unroll
        for (int j = 0; j < 4; j++) {
            unsigned b = os[j] >> 24;
            unsigned m = __match_any_sync(0xffffffffu, b);
            if (lane == __ffs(m) - 1) atomicAdd(&myh[b], __popc(m));
        }
    }
    float M = blk_reduce_max(lmax, redTmp);

    // merge 32 private hists -> h8f (float counts, exact)
    __syncthreads();
    if (t < NB1) {
        int s = 0;
        #pragma unroll
        for (int w2 = 0; w2 < 32; w2++) s += wh[w2 * NB1 + t];
        h8f[t] = (float)s;
    }

    // ---- Level-1 (8-bit) count select ----
    CrossRes r1 = find_crossing<NB1>(h8f, (float)k, scanTmp, &shr, &shb, &shc);
    unsigned b8 = (unsigned)r1.bin;
    float krem = (float)k - r1.above;     // rank target within bin b8
    unsigned long long hiFloor = ((unsigned long long)(b8 + 1)) << 24;

    // ---- Phase B (L2): 12-bit refine hist for bin b8 + compact "above" ----
    __syncthreads();   // retire wh reads before overlaying hist12
    for (int i = t; i < NB12; i += TPB) hist12[i] = 0.f;
    if (t == 0) shn = 0;
    __syncthreads();
    for (int i = t; i < NV4; i += TPB) {
        float4 v = lg4[i];
        float xs[4] = {v.x, v.y, v.z, v.w};
        #pragma unroll
        for (int j = 0; j < 4; j++) {
            float x = xs[j];
            unsigned ou = f2ord(x);
            bool above = ((unsigned long long)ou >= hiFloor);
            unsigned m = __ballot_sync(0xffffffffu, above);
            if (m) {
                int leader = __ffs(m) - 1;
                int base = 0;
                if (lane == leader) base = atomicAdd(&shn, __popc(m));
                base = __shfl_sync(0xffffffffu, base, leader);
                if (above) {
                    int off = base + __popc(m & ((1u << lane) - 1u));
                    if (off < CAND_MAX) cand[off] = x;
                }
            }
            if (!above && (ou >> 24) == b8)
                atomicAdd(&hist12[(ou >> 12) & 4095u], 1.f);
        }
    }

    // ---- Level-2 (12-bit) count select within bin b8 ----
    CrossRes r2 = find_crossing<NB12>(hist12, krem, scanTmp, &shr, &shb, &shc);
    unsigned c2 = (unsigned)r2.bin;
    float krem2 = krem - r2.above;
    unsigned pfx20 = (b8 << 12) | c2;     // top 20 bits of threshold

    // ---- Phase B2 (L2): compact bin-b8 tail (hi12 >= c2) into cand ----
    for (int i = t; i < NV4; i += TPB) {
        float4 v = lg4[i];
        float xs[4] = {v.x, v.y, v.z, v.w};
        #pragma unroll
        for (int j = 0; j < 4; j++) {
            float x = xs[j];
            unsigned ou = f2ord(x);
            bool take = ((ou >> 24) == b8) && (((ou >> 12) & 4095u) >= c2);
            unsigned m = __ballot_sync(0xffffffffu, take);
            if (m) {
                int leader = __ffs(m) - 1;
                int base = 0;
                if (lane == leader) base = atomicAdd(&shn, __popc(m));
                base = __shfl_sync(0xffffffffu, base, leader);
                if (take) {
                    int off = base + __popc(m & ((1u << lane) - 1u));
                    if (off < CAND_MAX) cand[off] = x;
                }
            }
        }
    }
    __syncthreads();
    int n = shn; if (n > CAND_MAX) n = CAND_MAX;

    // ---- Level-3 (final 12 bits) -> exact top-k threshold ----
    for (int i = t; i < NB12; i += TPB) hist12[i] = 0.f;
    __syncthreads();
    for (int i = t; i < n; i += TPB) {
        unsigned ou = f2ord(cand[i]);
        if ((ou >> 12) == pfx20) atomicAdd(&hist12[ou & 4095u], 1.f);
    }
    CrossRes r3 = find_crossing<NB12>(hist12, krem2, scanTmp, &shr, &shb, &shc);
    unsigned thr_ou = (pfx20 << 12) | (unsigned)r3.bin;

    // ---- Z_k over top-k set ----
    float zs = 0.f;
    for (int i = t; i < n; i += TPB) {
        float x = cand[i];
        if (f2ord(x) >= thr_ou) zs += __expf(x - M);
    }
    float Zk = blk_reduce_sum(zs, redTmp);
    float T = p * Zk;

    // ---- Weighted radix descent (12/10/10) for top-p cutoff ----
    __syncthreads();
    for (int i = t; i < NB12; i += TPB) hist12[i] = 0.f;
    __syncthreads();
    for (int i = t; i < n; i += TPB) {
        float x = cand[i]; unsigned ou = f2ord(x);
        if (ou >= thr_ou) atomicAdd(&hist12[ou >> 20], __expf(x - M));
    }
    CrossRes w1 = find_crossing<NB12>(hist12, T, scanTmp, &shr, &shb, &shc);
    unsigned t_ou;
    if (!w1.found) {
        t_ou = thr_ou;
    } else {
        float Tb = T - w1.above;
        unsigned c1 = (unsigned)w1.bin;
        for (int i = t; i < NB2; i += TPB) h2[i] = 0.f;
        __syncthreads();
        for (int i = t; i < n; i += TPB) {
            float x = cand[i]; unsigned ou = f2ord(x);
            if (ou >= thr_ou && (ou >> 20) == c1)
                atomicAdd(&h2[(ou >> 10) & 1023u], __expf(x - M));
        }
        CrossRes w2 = find_crossing<NB2>(h2, Tb, scanTmp, &shr, &shb, &shc);
        if (!w2.found) {
            t_ou = c1 << 20;
        } else {
            float T2 = Tb - w2.above;
            unsigned pw = (c1 << 10) | (unsigned)w2.bin;
            for (int i = t; i < NB2; i += TPB) h2[i] = 0.f;
            __syncthreads();
            for (int i = t; i < n; i += TPB) {
                float x = cand[i]; unsigned ou = f2ord(x);
                if (ou >= thr_ou && (ou >> 10) == pw)
                    atomicAdd(&h2[ou & 1023u], __expf(x - M));
            }
            CrossRes w3 = find_crossing<NB2>(h2, T2, scanTmp, &shr, &shb, &shc);
            t_ou = w3.found ? ((pw << 10) | (unsigned)w3.bin) : (pw << 10);
        }
    }
    unsigned f_ou = (t_ou > thr_ou) ? t_ou : thr_ou;

    // ---- Final normalizer ----
    float zf = 0.f;
    for (int i = t; i < n; i += TPB) {
        float x = cand[i];
        if (f2ord(x) >= f_ou) zf += __expf(x - M);
    }
    float Z = blk_reduce_sum(zf, redTmp);
    float invZ = 1.0f / Z;

    // ---- Phase E: write probs + fused Gumbel-max argmax ----
    const float4* q4 = reinterpret_cast<const float4*>(qr);
    float4* pr4 = reinterpret_cast<float4*>(pro);
    float bv = -1.f; int bi = 0x7fffffff;
    for (int i = t; i < NV4; i += TPB) {
        float4 lv = lg4[i];
        float xs[4] = {lv.x, lv.y, lv.z, lv.w};
        bool kept[4];
        bool anyk = false;
        #pragma unroll
        for (int j = 0; j < 4; j++) {
            kept[j] = (f2ord(xs[j]) >= f_ou);
            anyk |= kept[j];
        }
        if (__any_sync(0xffffffffu, anyk)) {
            float4 qv = q4[i];
            float qs[4] = {qv.x, qv.y, qv.z, qv.w};
            float ps[4];
            #pragma unroll
            for (int j = 0; j < 4; j++) {
                float prob = kept[j] ? __expf(xs[j] - M) * invZ : 0.0f;
                ps[j] = prob;
                if (kept[j]) {
                    float ratio = prob / (-__logf(qs[j]));
                    int idx = i * 4 + j;
                    if (ratio > bv || (ratio == bv && idx < bi)) { bv = ratio; bi = idx; }
                }
            }
            float4 ov; ov.x = ps[0]; ov.y = ps[1]; ov.z = ps[2]; ov.w = ps[3];
            pr4[i] = ov;
        } else {
            pr4[i] = make_float4(0.f, 0.f, 0.f, 0.f);
        }
    }
    // argmax reduce (first-index tie-break)
    #pragma unroll
    for (int o = 16; o; o >>= 1) {
        float ov = __shfl_down_sync(0xffffffffu, bv, o);
        int   oi = __shfl_down_sync(0xffffffffu, bi, o);
        if (ov > bv || (ov == bv && oi < bi)) { bv = ov; bi = oi; }
    }
    if (lane == 0) { argV[warp] = bv; argI[warp] = bi; }
    __syncthreads();
    if (warp == 0) {
        bv = argV[lane]; bi = argI[lane];
        #pragma unroll
        for (int o = 16; o; o >>= 1) {
            float ov = __shfl_down_sync(0xffffffffu, bv, o);
            int   oi = __shfl_down_sync(0xffffffffu, bi, o);
            if (ov > bv || (ov == bv && oi < bi)) { bv = ov; bi = oi; }
        }
        if (lane == 0) out_ids[row] = (float)bi;
    }
}

extern "C" void kernel_launch(void* const* d_in, const int* in_sizes, int n_in,
                              void* d_out, int out_size) {
    const float* logits = (const float*)d_in[0];
    const int*   k      = (const int*)  d_in[1];
    const float* p      = (const float*)d_in[2];
    const float* q      = (const float*)d_in[3];
    float* out = (float*)d_out;
    float* out_ids   = out;
    float* out_probs = out + BB;
    topk_topp_sample_kernel<<<BB, TPB>>>(logits, k, p, q, out_ids, out_probs);
}

// round 5
// speedup vs baseline: 1.9808x; 1.2300x over previous
#include <cuda_runtime.h>
#include <math.h>

#define BB   128
#define VV   128000
#define NV4  (VV/4)
#define TPB  1024
#define NB1  256     // level-1: top 8 bits of ordered key
#define NB12 4096    // 12-bit refine / weighted level-1
#define NB2  1024    // weighted levels 2/3
#define CAND_MAX 6144

// monotonic float -> ordered uint32
__device__ __forceinline__ unsigned f2ord(float f) {
    unsigned u = __float_as_uint(f);
    return (u & 0x80000000u) ? ~u : (u | 0x80000000u);
}
// inverse; guarded against NaN-zone keys (only reachable when floor <= -inf)
__device__ __forceinline__ float ord2f_floor(unsigned o) {
    if (o <= 0x007FFFFFu) return -__int_as_float(0x7f800000); // -inf: take all
    return (o & 0x80000000u) ? __uint_as_float(o ^ 0x80000000u)
                             : __uint_as_float(~o);
}

__device__ float blk_excl_scan(float v, float* tmp) {
    __syncthreads();
    int lane = threadIdx.x & 31, w = threadIdx.x >> 5;
    float x = v;
    #pragma unroll
    for (int o = 1; o < 32; o <<= 1) {
        float y = __shfl_up_sync(0xffffffffu, x, o);
        if (lane >= o) x += y;
    }
    if (lane == 31) tmp[w] = x;
    __syncthreads();
    if (w == 0) {
        float s = tmp[lane];
        #pragma unroll
        for (int o = 1; o < 32; o <<= 1) {
            float y = __shfl_up_sync(0xffffffffu, s, o);
            if (lane >= o) s += y;
        }
        tmp[lane] = s;
    }
    __syncthreads();
    float pre = (w > 0) ? tmp[w - 1] : 0.0f;
    return pre + x - v;
}

__device__ float blk_reduce_sum(float v, float* tmp) {
    __syncthreads();
    int lane = threadIdx.x & 31, w = threadIdx.x >> 5;
    #pragma unroll
    for (int o = 16; o; o >>= 1) v += __shfl_xor_sync(0xffffffffu, v, o);
    if (lane == 0) tmp[w] = v;
    __syncthreads();
    if (w == 0) {
        float x = tmp[lane];
        #pragma unroll
        for (int o = 16; o; o >>= 1) x += __shfl_xor_sync(0xffffffffu, x, o);
        if (lane == 0) tmp[0] = x;
    }
    __syncthreads();
    return tmp[0];
}

__device__ float blk_reduce_max(float v, float* tmp) {
    __syncthreads();
    int lane = threadIdx.x & 31, w = threadIdx.x >> 5;
    #pragma unroll
    for (int o = 16; o; o >>= 1) v = fmaxf(v, __shfl_xor_sync(0xffffffffu, v, o));
    if (lane == 0) tmp[w] = v;
    __syncthreads();
    if (w == 0) {
        float x = tmp[lane];
        #pragma unroll
        for (int o = 16; o; o >>= 1) x = fmaxf(x, __shfl_xor_sync(0xffffffffu, x, o));
        if (lane == 0) tmp[0] = x;
    }
    __syncthreads();
    return tmp[0];
}

struct CrossRes { int bin; float above; bool found; };

template<int NBINS>
__device__ CrossRes find_crossing(const float* wgt, float target, float* scanTmp,
                                  int* sh_r, int* sh_b, float* sh_c) {
    __syncthreads();
    const int bpt = (NBINS + TPB - 1) / TPB;
    int t = threadIdx.x;
    float s = 0.f;
    #pragma unroll
    for (int j = 0; j < bpt; j++) {
        int r = t * bpt + j;
        if (r < NBINS) s += wgt[NBINS - 1 - r];
    }
    float P = blk_excl_scan(s, scanTmp);
    if (t == 0) *sh_r = 0x7fffffff;
    __syncthreads();
    float cum = P;
    #pragma unroll
    for (int j = 0; j < bpt; j++) {
        int r = t * bpt + j;
        if (r < NBINS) {
            float wv = wgt[NBINS - 1 - r];
            if (cum < target && cum + wv >= target) atomicMin(sh_r, r);
            cum += wv;
        }
    }
    __syncthreads();
    int fr = *sh_r;
    if (fr != 0x7fffffff) {
        cum = P;
        #pragma unroll
        for (int j = 0; j < bpt; j++) {
            int r = t * bpt + j;
            if (r < NBINS) {
                float wv = wgt[NBINS - 1 - r];
                if (r == fr) { *sh_b = NBINS - 1 - r; *sh_c = cum; }
                cum += wv;
            }
        }
    }
    __syncthreads();
    CrossRes res;
    res.found = (fr != 0x7fffffff);
    res.bin = res.found ? *sh_b : 0;
    res.above = res.found ? *sh_c : 0.f;
    return res;
}

__global__ void __launch_bounds__(TPB, 1)
topk_topp_sample_kernel(const float* __restrict__ logits,
                        const int*   __restrict__ karr,
                        const float* __restrict__ parr,
                        const float* __restrict__ qarr,
                        float* __restrict__ out_ids,
                        float* __restrict__ out_probs)
{
    // 40 KB union: phase A = 32 warp-private 256-bin int hists (32 KB);
    // later = hist12[4096] floats (16 KB) + cand[6144] floats (24 KB).
    __shared__ __align__(16) unsigned char sbuf[40960];
    __shared__ float h2[NB2];
    __shared__ float h8f[NB1];
    __shared__ float scanTmp[32];
    __shared__ float redTmp[32];
    __shared__ int   shr; __shared__ int shb; __shared__ float shc;
    __shared__ int   shn;
    __shared__ float argV[32]; __shared__ int argI[32];

    int*   wh     = reinterpret_cast<int*>(sbuf);            // [32][256]
    float* hist12 = reinterpret_cast<float*>(sbuf);          // [4096]
    float* cand   = reinterpret_cast<float*>(sbuf + 16384);  // [6144]

    const int row = blockIdx.x;
    const int t = threadIdx.x;
    const int lane = t & 31, warp = t >> 5;
    const float* lg = logits + (long long)row * VV;
    const float* qr = qarr   + (long long)row * VV;
    float* pro = out_probs + (long long)row * VV;
    const int   k = karr[row];
    const float p = parr[row];

    // ---- Phase A: per-warp-private 8-bit histogram ----
    for (int i = t; i < 32 * NB1; i += TPB) wh[i] = 0;
    __syncthreads();

    const float4* lg4 = reinterpret_cast<const float4*>(lg);
    int* myh = wh + warp * NB1;
    for (int i = t; i < NV4; i += TPB) {
        float4 v = lg4[i];
        unsigned os[4] = { f2ord(v.x), f2ord(v.y), f2ord(v.z), f2ord(v.w) };
        #pragma unroll
        for (int j = 0; j < 4; j++) {
            unsigned b = os[j] >> 24;
            unsigned m = __match_any_sync(0xffffffffu, b);
            if (lane == __ffs(m) - 1) atomicAdd(&myh[b], __popc(m));
        }
    }
    __syncthreads();
    if (t < NB1) {
        int s = 0;
        #pragma unroll
        for (int w2 = 0; w2 < 32; w2++) s += wh[w2 * NB1 + t];
        h8f[t] = (float)s;
    }

    // ---- Level-1 (8-bit) count select ----
    CrossRes r1 = find_crossing<NB1>(h8f, (float)k, scanTmp, &shr, &shb, &shc);
    unsigned b8 = (unsigned)r1.bin;
    float krem = (float)k - r1.above;             // rank target within bin b8
    const float ffloor = ord2f_floor(b8 << 24);   // float-domain bin floor

    // ---- Phase B (L2): compact everything >= bin-b8 floor into smem ----
    __syncthreads();   // retire wh reads before overlaying cand/hist12
    if (t == 0) shn = 0;
    __syncthreads();
    for (int i = t; i < NV4; i += TPB) {
        float4 v = lg4[i];
        float xs[4] = {v.x, v.y, v.z, v.w};
        float loc[4]; int cnt = 0;
        #pragma unroll
        for (int j = 0; j < 4; j++)
            if (xs[j] >= ffloor) loc[cnt++] = xs[j];
        if (cnt) {
            int base = atomicAdd(&shn, cnt);
            #pragma unroll
            for (int c = 0; c < 4; c++)
                if (c < cnt && base + c < CAND_MAX) cand[base + c] = loc[c];
        }
    }
    __syncthreads();
    int n = shn; if (n > CAND_MAX) n = CAND_MAX;

    // ---- Row max from candidates (max is guaranteed in cand) ----
    float mx = -3.4e38f;
    for (int i = t; i < n; i += TPB) mx = fmaxf(mx, cand[i]);
    float M = blk_reduce_max(mx, redTmp);

    // ---- Level-2 (12-bit) count select within bin b8 ----
    for (int i = t; i < NB12; i += TPB) hist12[i] = 0.f;
    __syncthreads();
    for (int i = t; i < n; i += TPB) {
        unsigned ou = f2ord(cand[i]);
        if ((ou >> 24) == b8) atomicAdd(&hist12[(ou >> 12) & 4095u], 1.f);
    }
    CrossRes r2 = find_crossing<NB12>(hist12, krem, scanTmp, &shr, &shb, &shc);
    unsigned c2 = (unsigned)r2.bin;
    float krem2 = krem - r2.above;
    unsigned pfx20 = (b8 << 12) | c2;

    // ---- Level-3 (final 12 bits) -> exact top-k threshold ----
    for (int i = t; i < NB12; i += TPB) hist12[i] = 0.f;
    __syncthreads();
    for (int i = t; i < n; i += TPB) {
        unsigned ou = f2ord(cand[i]);
        if ((ou >> 12) == pfx20) atomicAdd(&hist12[ou & 4095u], 1.f);
    }
    CrossRes r3 = find_crossing<NB12>(hist12, krem2, scanTmp, &shr, &shb, &shc);
    unsigned thr_ou = (pfx20 << 12) | (unsigned)r3.bin;

    // ---- Z_k over top-k set ----
    float zs = 0.f;
    for (int i = t; i < n; i += TPB) {
        float x = cand[i];
        if (f2ord(x) >= thr_ou) zs += __expf(x - M);
    }
    float Zk = blk_reduce_sum(zs, redTmp);
    float T = p * Zk;

    // ---- Weighted radix descent (12/10/10) for top-p cutoff ----
    __syncthreads();
    for (int i = t; i < NB12; i += TPB) hist12[i] = 0.f;
    __syncthreads();
    for (int i = t; i < n; i += TPB) {
        float x = cand[i]; unsigned ou = f2ord(x);
        if (ou >= thr_ou) atomicAdd(&hist12[ou >> 20], __expf(x - M));
    }
    CrossRes w1 = find_crossing<NB12>(hist12, T, scanTmp, &shr, &shb, &shc);
    unsigned t_ou;
    if (!w1.found) {
        t_ou = thr_ou;
    } else {
        float Tb = T - w1.above;
        unsigned c1 = (unsigned)w1.bin;
        for (int i = t; i < NB2; i += TPB) h2[i] = 0.f;
        __syncthreads();
        for (int i = t; i < n; i += TPB) {
            float x = cand[i]; unsigned ou = f2ord(x);
            if (ou >= thr_ou && (ou >> 20) == c1)
                atomicAdd(&h2[(ou >> 10) & 1023u], __expf(x - M));
        }
        CrossRes w2 = find_crossing<NB2>(h2, Tb, scanTmp, &shr, &shb, &shc);
        if (!w2.found) {
            t_ou = c1 << 20;
        } else {
            float T2 = Tb - w2.above;
            unsigned pw = (c1 << 10) | (unsigned)w2.bin;
            for (int i = t; i < NB2; i += TPB) h2[i] = 0.f;
            __syncthreads();
            for (int i = t; i < n; i += TPB) {
                float x = cand[i]; unsigned ou = f2ord(x);
                if (ou >= thr_ou && (ou >> 10) == pw)
                    atomicAdd(&h2[ou & 1023u], __expf(x - M));
            }
            CrossRes w3 = find_crossing<NB2>(h2, T2, scanTmp, &shr, &shb, &shc);
            t_ou = w3.found ? ((pw << 10) | (unsigned)w3.bin) : (pw << 10);
        }
    }
    unsigned f_ou = (t_ou > thr_ou) ? t_ou : thr_ou;
    const float ford = ord2f_floor(f_ou);   // float-domain final threshold

    // ---- Final normalizer ----
    float zf = 0.f;
    for (int i = t; i < n; i += TPB) {
        float x = cand[i];
        if (x >= ford) zf += __expf(x - M);
    }
    float Z = blk_reduce_sum(zf, redTmp);
    float invZ = 1.0f / Z;

    // ---- Phase E: write probs + fused Gumbel-max argmax ----
    const float4* q4 = reinterpret_cast<const float4*>(qr);
    float4* pr4 = reinterpret_cast<float4*>(pro);
    float bv = -1.f; int bi = 0x7fffffff;
    for (int i = t; i < NV4; i += TPB) {
        float4 lv = lg4[i];
        float xs[4] = {lv.x, lv.y, lv.z, lv.w};
        bool kept[4];
        bool anyk = false;
        #pragma unroll
        for (int j = 0; j < 4; j++) {
            kept[j] = (xs[j] >= ford);
            anyk |= kept[j];
        }
        if (__any_sync(0xffffffffu, anyk)) {
            float4 qv = q4[i];
            float qs[4] = {qv.x, qv.y, qv.z, qv.w};
            float ps[4];
            #pragma unroll
            for (int j = 0; j < 4; j++) {
                float prob = kept[j] ? __expf(xs[j] - M) * invZ : 0.0f;
                ps[j] = prob;
                if (kept[j]) {
                    float ratio = prob / (-__logf(qs[j]));
                    int idx = i * 4 + j;
                    if (ratio > bv || (ratio == bv && idx < bi)) { bv = ratio; bi = idx; }
                }
            }
            float4 ov; ov.x = ps[0]; ov.y = ps[1]; ov.z = ps[2]; ov.w = ps[3];
            pr4[i] = ov;
        } else {
            pr4[i] = make_float4(0.f, 0.f, 0.f, 0.f);
        }
    }
    // argmax reduce (first-index tie-break)
    #pragma unroll
    for (int o = 16; o; o >>= 1) {
        float ov = __shfl_down_sync(0xffffffffu, bv, o);
        int   oi = __shfl_down_sync(0xffffffffu, bi, o);
        if (ov > bv || (ov == bv && oi < bi)) { bv = ov; bi = oi; }
    }
    if (lane == 0) { argV[warp] = bv; argI[warp] = bi; }
    __syncthreads();
    if (warp == 0) {
        bv = argV[lane]; bi = argI[lane];
        #pragma unroll
        for (int o = 16; o; o >>= 1) {
            float ov = __shfl_down_sync(0xffffffffu, bv, o);
            int   oi = __shfl_down_sync(0xffffffffu, bi, o);
            if (ov > bv || (ov == bv && oi < bi)) { bv = ov; bi = oi; }
        }
        if (lane == 0) out_ids[row] = (float)bi;
    }
}

extern "C" void kernel_launch(void* const* d_in, const int* in_sizes, int n_in,
                              void* d_out, int out_size) {
    const float* logits = (const float*)d_in[0];
    const int*   k      = (const int*)  d_in[1];
    const float* p      = (const float*)d_in[2];
    const float* q      = (const float*)d_in[3];
    float* out = (float*)d_out;
    float* out_ids   = out;
    float* out_probs = out + BB;
    topk_topp_sample_kernel<<<BB, TPB>>>(logits, k, p, q, out_ids, out_probs);
}